// round 14
// baseline (speedup 1.0000x reference)
#include <cuda_runtime.h>
#include <cuda_fp16.h>
#include <mma.h>
#include <math.h>

using namespace nvcuda;

#define N_NODES   50000
#define E_EDGES   1600000
#define E4        (E_EDGES / 4)
#define EP        (E_EDGES + N_NODES)
#define NHEADS    4
#define HC        128
#define HC4       32
#define NGRAPH    64

#define LDA 40      // half elements per As row
#define LDB 136     // half elements per Bs row
#define LDC 132     // float elements per Cs row

#define GEMM_BLOCKS ((N_NODES + 63) / 64)              // 782
#define FILL_BLOCKS ((E4 + N_NODES + 255) / 256)

// ---------------- scratch ------------------------------------------------------
__device__ uint4  g_h16[N_NODES * 16];    // transformed features, fp16x8 per slot
__device__ float4 g_agg4[N_NODES * HC4];  // aggregation output (fp32)
__device__ float4 g_asrc4[N_NODES];
__device__ float4 g_adst4[N_NODES];
__device__ int    g_deg[N_NODES];         // zero-init at load; scan re-zeros each run
__device__ int    g_rowptr[N_NODES + 1];
__device__ int    g_fill[N_NODES];
__device__ int    g_esrc[EP];
__device__ float  g_pool[NGRAPH * HC];
__device__ float  g_cnt[NGRAPH];

// ---------------- helpers ------------------------------------------------------
__device__ __forceinline__ float lrelu(float v) { return v > 0.f ? v : 0.2f * v; }
__device__ __forceinline__ float comp4(float4 v, int i) {
    return i == 0 ? v.x : (i == 1 ? v.y : (i == 2 ? v.z : v.w));
}
__device__ __forceinline__ int clampN(int v) {
    return v < 0 ? 0 : (v >= N_NODES ? N_NODES - 1 : v);
}

// ---------------- zero pool ------------------------------------------------------
__global__ void zero_pool_kernel() {
    int i = blockIdx.x * blockDim.x + threadIdx.x;
    if (i < NGRAPH * HC) g_pool[i] = 0.f;
    if (i < NGRAPH) g_cnt[i] = 0.f;
}

// ---------------- build CSR (counting sort by dst) -----------------------------
__global__ void hist_kernel(const int* __restrict__ ei) {
    int i = blockIdx.x * blockDim.x + threadIdx.x;
    if (i >= E4) return;
    int4 d4 = ((const int4*)(ei + E_EDGES))[i];
    atomicAdd(&g_deg[clampN(d4.x)], 1);
    atomicAdd(&g_deg[clampN(d4.y)], 1);
    atomicAdd(&g_deg[clampN(d4.z)], 1);
    atomicAdd(&g_deg[clampN(d4.w)], 1);
}

#define SCAN_PER ((N_NODES + 1023) / 1024)    // 49
__global__ void scan_kernel() {
    __shared__ int buf[1024];
    int tid  = threadIdx.x;
    int base = tid * SCAN_PER;
    int lim  = min(base + SCAN_PER, N_NODES);
    int sum = 0;
    for (int i = base; i < lim; ++i) sum += g_deg[i] + 1;   // +1 self loop
    buf[tid] = sum;
    __syncthreads();
    for (int off = 1; off < 1024; off <<= 1) {
        int t = (tid >= off) ? buf[tid - off] : 0;
        __syncthreads();
        buf[tid] += t;
        __syncthreads();
    }
    int run = buf[tid] - sum;
    for (int i = base; i < lim; ++i) {
        g_rowptr[i] = run;
        g_fill[i]   = run;
        run += g_deg[i] + 1;
        g_deg[i] = 0;          // restore for next replay (deterministic)
    }
    if (tid == 1023) g_rowptr[N_NODES] = buf[1023];
}

// ---------------- fp16 tensor-core GEMM + fused attention (device body) --------
struct SmemAB { __half Ah[64][LDA]; __half Bh[32][LDB]; };
union SmemU { SmemAB ab; float Cs[64][LDC]; };

__device__ __forceinline__ void gemm_att_body(
    SmemU& sh, int blk,
    const float* __restrict__ Ap, const float* __restrict__ B,
    const float* __restrict__ att_src, const float* __restrict__ att_dst, int M) {
    int tid = threadIdx.x;
    int wid = tid >> 5;
    int wm = wid & 3;
    int wn = wid >> 2;
    int bm0 = blk * 64;

    wmma::fragment<wmma::accumulator, 16, 16, 16, float> acc[4];
#pragma unroll
    for (int j = 0; j < 4; ++j) wmma::fill_fragment(acc[j], 0.f);

    for (int kt = 0; kt < 4; ++kt) {
#pragma unroll
        for (int t = 0; t < 2; ++t) {
            int id = tid + t * 256;
            int r  = id >> 3;
            int c4 = (id & 7) * 4;
            int gr = bm0 + r;
            float4 v = (gr < M) ? ((const float4*)&Ap[gr * 128 + kt * 32])[c4 >> 2]
                                : make_float4(0.f, 0.f, 0.f, 0.f);
            __half2 lo = __floats2half2_rn(v.x, v.y);
            __half2 hi = __floats2half2_rn(v.z, v.w);
            *(__half2*)&sh.ab.Ah[r][c4]     = lo;
            *(__half2*)&sh.ab.Ah[r][c4 + 2] = hi;
        }
#pragma unroll
        for (int t = 0; t < 4; ++t) {
            int id  = tid + t * 256;
            int row = id >> 5;
            int c4  = (id & 31) * 4;
            float4 v = ((const float4*)&B[(kt * 32 + row) * 128])[c4 >> 2];
            __half2 lo = __floats2half2_rn(v.x, v.y);
            __half2 hi = __floats2half2_rn(v.z, v.w);
            *(__half2*)&sh.ab.Bh[row][c4]     = lo;
            *(__half2*)&sh.ab.Bh[row][c4 + 2] = hi;
        }
        __syncthreads();
#pragma unroll
        for (int ks = 0; ks < 2; ++ks) {
            wmma::fragment<wmma::matrix_a, 16, 16, 16, __half, wmma::row_major> a;
            wmma::load_matrix_sync(a, &sh.ab.Ah[wm * 16][ks * 16], LDA);
#pragma unroll
            for (int j = 0; j < 4; ++j) {
                wmma::fragment<wmma::matrix_b, 16, 16, 16, __half, wmma::row_major> b;
                wmma::load_matrix_sync(b, &sh.ab.Bh[ks * 16][wn * 64 + j * 16], LDB);
                wmma::mma_sync(acc[j], a, b, acc[j]);
            }
        }
        __syncthreads();
    }

#pragma unroll
    for (int j = 0; j < 4; ++j)
        wmma::store_matrix_sync(&sh.Cs[wm * 16][wn * 64 + j * 16], acc[j], LDC,
                                wmma::mem_row_major);
    __syncthreads();

    // fused attention coefficients
    {
        int r  = tid >> 2;
        int hd = tid & 3;
        int gr = bm0 + r;
        if (gr < M) {
            float s = 0.f, d = 0.f;
#pragma unroll
            for (int i = 0; i < 32; ++i) {
                float v = sh.Cs[r][hd * 32 + i];
                s += v * att_src[hd * 32 + i];
                d += v * att_dst[hd * 32 + i];
            }
            ((float*)g_asrc4)[gr * 4 + hd] = s;
            ((float*)g_adst4)[gr * 4 + hd] = d;
        }
    }

    // write h as fp16x8 slots
#pragma unroll
    for (int t = 0; t < 4; ++t) {
        int id  = tid + t * 256;
        int row = id >> 4;
        int sl  = id & 15;
        int gr  = bm0 + row;
        if (gr < M) {
            float4 v0 = *(const float4*)&sh.Cs[row][sl * 8];
            float4 v1 = *(const float4*)&sh.Cs[row][sl * 8 + 4];
            __half2 a = __floats2half2_rn(v0.x, v0.y);
            __half2 b = __floats2half2_rn(v0.z, v0.w);
            __half2 c = __floats2half2_rn(v1.x, v1.y);
            __half2 d = __floats2half2_rn(v1.z, v1.w);
            uint4 u;
            u.x = *(unsigned*)&a; u.y = *(unsigned*)&b;
            u.z = *(unsigned*)&c; u.w = *(unsigned*)&d;
            g_h16[gr * 16 + sl] = u;
        }
    }
}

// fill body (device)
__device__ __forceinline__ void fill_body(int i, const int* __restrict__ ei) {
    if (i < E4) {
        int4 s4 = ((const int4*)ei)[i];
        int4 d4 = ((const int4*)(ei + E_EDGES))[i];
        int p;
        p = atomicAdd(&g_fill[clampN(d4.x)], 1); if (p >= 0 && p < EP) g_esrc[p] = clampN(s4.x);
        p = atomicAdd(&g_fill[clampN(d4.y)], 1); if (p >= 0 && p < EP) g_esrc[p] = clampN(s4.y);
        p = atomicAdd(&g_fill[clampN(d4.z)], 1); if (p >= 0 && p < EP) g_esrc[p] = clampN(s4.z);
        p = atomicAdd(&g_fill[clampN(d4.w)], 1); if (p >= 0 && p < EP) g_esrc[p] = clampN(s4.w);
    } else {
        int n = i - E4;
        if (n < N_NODES) {
            int p = atomicAdd(&g_fill[n], 1);
            if (p >= 0 && p < EP) g_esrc[p] = n;
        }
    }
}

// fused: blocks [0, GEMM_BLOCKS) do gemm1+att, the rest do fill
__global__ void gemm1_fill_kernel(const float* __restrict__ x,
                                  const float* __restrict__ W1,
                                  const float* __restrict__ att_src,
                                  const float* __restrict__ att_dst,
                                  const int* __restrict__ ei) {
    __shared__ __align__(16) SmemU sh;
    if (blockIdx.x < GEMM_BLOCKS) {
        gemm_att_body(sh, blockIdx.x, x, W1, att_src, att_dst, N_NODES);
    } else {
        int i = (blockIdx.x - GEMM_BLOCKS) * blockDim.x + threadIdx.x;
        fill_body(i, ei);
    }
}

// standalone gemm (layer 2)
__global__ void gemm_att_kernel(const float* __restrict__ B,
                                const float* __restrict__ att_src,
                                const float* __restrict__ att_dst) {
    __shared__ __align__(16) SmemU sh;
    gemm_att_body(sh, blockIdx.x, (const float*)g_agg4, B, att_src, att_dst, N_NODES);
}

// ---------------- GAT aggregation: warp/node, 2 edges per iteration ------------
__global__ void agg_kernel(const float* __restrict__ bias) {
    __shared__ float4 s_alpha[8][32];
    __shared__ int    s_src[8][33];
    int wband = threadIdx.x >> 5;
    int w = (blockIdx.x * blockDim.x + threadIdx.x) >> 5;
    if (w >= N_NODES) return;
    int lane = threadIdx.x & 31;
    int l16    = lane & 15;
    int half16 = lane >> 4;
    int hd2    = l16 >> 2;
    int beg = g_rowptr[w];
    int end = g_rowptr[w + 1];
    float4 ad = g_adst4[w];

    float4 acc0 = make_float4(0.f, 0.f, 0.f, 0.f);
    float4 acc1 = make_float4(0.f, 0.f, 0.f, 0.f);
    float4 den  = make_float4(0.f, 0.f, 0.f, 0.f);

    int    cur_s  = 0;
    float4 cur_as = make_float4(0.f, 0.f, 0.f, 0.f);
    if (beg + lane < end) {
        cur_s  = g_esrc[beg + lane];
        cur_as = g_asrc4[cur_s];
    }

    for (int j0 = beg; j0 < end; j0 += 32) {
        int cnt = min(32, end - j0);
        if (lane < cnt) {
            float4 ex;
            ex.x = __expf(lrelu(cur_as.x + ad.x));
            ex.y = __expf(lrelu(cur_as.y + ad.y));
            ex.z = __expf(lrelu(cur_as.z + ad.z));
            ex.w = __expf(lrelu(cur_as.w + ad.w));
            den.x += ex.x; den.y += ex.y; den.z += ex.z; den.w += ex.w;
            s_alpha[wband][lane] = ex;
            s_src[wband][lane]   = cur_s;
        }
        __syncwarp();

        int nj = j0 + 32;
        int    nxt_s  = 0;
        float4 nxt_as = make_float4(0.f, 0.f, 0.f, 0.f);
        if (nj + lane < end) {
            nxt_s  = g_esrc[nj + lane];
            nxt_as = g_asrc4[nxt_s];
        }

#pragma unroll 4
        for (int t = 0; t < cnt; t += 2) {
            int te = t + half16;
            float wgt = 0.f;
            int s = 0;
            if (te < cnt) {
                wgt = ((const float*)&s_alpha[wband][te])[hd2];
                s   = s_src[wband][te];
            }
            uint4 u = g_h16[s * 16 + l16];
            float2 f0 = __half22float2(*(__half2*)&u.x);
            float2 f1 = __half22float2(*(__half2*)&u.y);
            float2 f2 = __half22float2(*(__half2*)&u.z);
            float2 f3 = __half22float2(*(__half2*)&u.w);
            acc0.x += f0.x * wgt; acc0.y += f0.y * wgt;
            acc0.z += f1.x * wgt; acc0.w += f1.y * wgt;
            acc1.x += f2.x * wgt; acc1.y += f2.y * wgt;
            acc1.z += f3.x * wgt; acc1.w += f3.y * wgt;
        }
        __syncwarp();
        cur_s = nxt_s; cur_as = nxt_as;
    }

#pragma unroll
    for (int off = 16; off; off >>= 1) {
        den.x += __shfl_xor_sync(0xffffffffu, den.x, off);
        den.y += __shfl_xor_sync(0xffffffffu, den.y, off);
        den.z += __shfl_xor_sync(0xffffffffu, den.z, off);
        den.w += __shfl_xor_sync(0xffffffffu, den.w, off);
    }

    acc0.x += __shfl_xor_sync(0xffffffffu, acc0.x, 16);
    acc0.y += __shfl_xor_sync(0xffffffffu, acc0.y, 16);
    acc0.z += __shfl_xor_sync(0xffffffffu, acc0.z, 16);
    acc0.w += __shfl_xor_sync(0xffffffffu, acc0.w, 16);
    acc1.x += __shfl_xor_sync(0xffffffffu, acc1.x, 16);
    acc1.y += __shfl_xor_sync(0xffffffffu, acc1.y, 16);
    acc1.z += __shfl_xor_sync(0xffffffffu, acc1.z, 16);
    acc1.w += __shfl_xor_sync(0xffffffffu, acc1.w, 16);

    if (half16 == 0) {
        float inv = 1.f / (comp4(den, hd2) + 1e-16f);
        acc0.x *= inv; acc0.y *= inv; acc0.z *= inv; acc0.w *= inv;
        acc1.x *= inv; acc1.y *= inv; acc1.z *= inv; acc1.w *= inv;
        if (bias) {
            const float* bp = bias + l16 * 8;
            float v;
            v = acc0.x + bp[0]; acc0.x = v > 0.f ? v : (__expf(v) - 1.f);
            v = acc0.y + bp[1]; acc0.y = v > 0.f ? v : (__expf(v) - 1.f);
            v = acc0.z + bp[2]; acc0.z = v > 0.f ? v : (__expf(v) - 1.f);
            v = acc0.w + bp[3]; acc0.w = v > 0.f ? v : (__expf(v) - 1.f);
            v = acc1.x + bp[4]; acc1.x = v > 0.f ? v : (__expf(v) - 1.f);
            v = acc1.y + bp[5]; acc1.y = v > 0.f ? v : (__expf(v) - 1.f);
            v = acc1.z + bp[6]; acc1.z = v > 0.f ? v : (__expf(v) - 1.f);
            v = acc1.w + bp[7]; acc1.w = v > 0.f ? v : (__expf(v) - 1.f);
        }
        g_agg4[w * HC4 + l16 * 2]     = acc0;
        g_agg4[w * HC4 + l16 * 2 + 1] = acc1;
    }
}

// ---------------- global mean pool (batch is sorted, int32) --------------------
__global__ void pool_kernel(const int* __restrict__ batch) {
    const float* feats = (const float*)g_agg4;
    int c  = threadIdx.x;
    int n0 = blockIdx.x * 128;
    int n1 = min(n0 + 128, N_NODES);
    if (n0 >= N_NODES) return;
    float acc = 0.f;
    int curg = batch[n0] & (NGRAPH - 1);
    int cnt_local = 0;
    for (int n = n0; n < n1; ++n) {
        int g = batch[n] & (NGRAPH - 1);
        if (g != curg) {
            atomicAdd(&g_pool[curg * HC + c], acc);
            if (c == 0) atomicAdd(&g_cnt[curg], (float)cnt_local);
            acc = 0.f; cnt_local = 0; curg = g;
        }
        acc += feats[n * HC + c];
        cnt_local++;
    }
    atomicAdd(&g_pool[curg * HC + c], acc);
    if (c == 0) atomicAdd(&g_cnt[curg], (float)cnt_local);
}

// ---------------- FC + log_softmax ---------------------------------------------
__global__ void final_kernel(const float* __restrict__ fcW, const float* __restrict__ fcb,
                             const float* __restrict__ b2, float* __restrict__ out) {
    __shared__ float sh[128 * 8 + 8];
    int g = blockIdx.x;
    int c = threadIdx.x;
    float cnt = g_cnt[g];
    float mean = 0.f;
    if (cnt > 0.f) mean = g_pool[g * HC + c] / cnt + b2[c];
#pragma unroll
    for (int j = 0; j < 8; ++j) sh[c * 8 + j] = mean * fcW[c * 8 + j];
    __syncthreads();
    if (c < 8) {
        float s = fcb[c];
        for (int k = 0; k < 128; ++k) s += sh[k * 8 + c];
        sh[1024 + c] = s;
    }
    __syncthreads();
    if (c == 0) {
        float mx = sh[1024];
#pragma unroll
        for (int j = 1; j < 8; ++j) mx = fmaxf(mx, sh[1024 + j]);
        float se = 0.f;
#pragma unroll
        for (int j = 0; j < 8; ++j) se += __expf(sh[1024 + j] - mx);
        float lse = logf(se) + mx;
#pragma unroll
        for (int j = 0; j < 8; ++j) out[g * 8 + j] = sh[1024 + j] - lse;
    }
}

// ---------------- launch --------------------------------------------------------
extern "C" void kernel_launch(void* const* d_in, const int* in_sizes, int n_in,
                              void* d_out, int out_size) {
    const float* x        = (const float*)d_in[0];
    const int*   ei       = (const int*)d_in[1];
    const int*   batch    = (const int*)d_in[2];
    const float* W1       = (const float*)d_in[3];
    const float* att_src1 = (const float*)d_in[4];
    const float* att_dst1 = (const float*)d_in[5];
    const float* b1       = (const float*)d_in[6];
    const float* W2       = (const float*)d_in[7];
    const float* att_src2 = (const float*)d_in[8];
    const float* att_dst2 = (const float*)d_in[9];
    const float* b2       = (const float*)d_in[10];
    const float* fcW      = (const float*)d_in[11];
    const float* fcb      = (const float*)d_in[12];
    float*       out      = (float*)d_out;

    // 0: hist, 1: scan, 2: fused gemm1+fill, 3: agg1  (ncu profiles slot 3)
    hist_kernel<<<(E4 + 255) / 256, 256>>>(ei);
    scan_kernel<<<1, 1024>>>();
    gemm1_fill_kernel<<<GEMM_BLOCKS + FILL_BLOCKS, 256>>>(x, W1, att_src1, att_dst1, ei);
    agg_kernel<<<(N_NODES + 7) / 8, 256>>>(b1);

    gemm_att_kernel<<<GEMM_BLOCKS, 256>>>(W2, att_src2, att_dst2);
    agg_kernel<<<(N_NODES + 7) / 8, 256>>>(nullptr);

    zero_pool_kernel<<<(NGRAPH * HC + 255) / 256, 256>>>();
    pool_kernel<<<(N_NODES + 127) / 128, 128>>>(batch);
    final_kernel<<<NGRAPH, 128>>>(fcW, fcb, b2, out);
}

// round 15
// speedup vs baseline: 1.0006x; 1.0006x over previous
#include <cuda_runtime.h>
#include <cuda_fp16.h>
#include <mma.h>
#include <math.h>

using namespace nvcuda;

#define N_NODES   50000
#define E_EDGES   1600000
#define E4        (E_EDGES / 4)
#define EP        (E_EDGES + N_NODES)
#define NHEADS    4
#define HC        128
#define HC4       32
#define NGRAPH    64

#define LDA 40
#define LDB 136
#define LDC 132

// ---------------- scratch ------------------------------------------------------
__device__ uint4  g_h16[N_NODES * 16];    // transformed features, fp16x8 per slot
__device__ float4 g_agg4[N_NODES * HC4];  // aggregation output (fp32)
__device__ float4 g_asrc4[N_NODES];
__device__ float4 g_adst4[N_NODES];
__device__ int    g_deg[N_NODES];         // zero at load; scan re-zeros each run
__device__ int    g_rowptr[N_NODES + 1];
__device__ int    g_fill[N_NODES];
__device__ int    g_esrc[EP];
__device__ float  g_pool[NGRAPH * HC];
__device__ float  g_cnt[NGRAPH];

// ---------------- helpers ------------------------------------------------------
__device__ __forceinline__ float lrelu(float v) { return v > 0.f ? v : 0.2f * v; }
__device__ __forceinline__ float comp4(float4 v, int i) {
    return i == 0 ? v.x : (i == 1 ? v.y : (i == 2 ? v.z : v.w));
}
__device__ __forceinline__ int clampN(int v) {
    return v < 0 ? 0 : (v >= N_NODES ? N_NODES - 1 : v);
}

// ---------------- zero pool ------------------------------------------------------
__global__ void zero_pool_kernel() {
    int i = blockIdx.x * blockDim.x + threadIdx.x;
    if (i < NGRAPH * HC) g_pool[i] = 0.f;
    if (i < NGRAPH) g_cnt[i] = 0.f;
}

// ---------------- build CSR (counting sort by dst) -----------------------------
__global__ void hist_kernel(const int* __restrict__ ei) {
    int i = blockIdx.x * blockDim.x + threadIdx.x;
    if (i >= E4) return;
    int4 d4 = ((const int4*)(ei + E_EDGES))[i];
    atomicAdd(&g_deg[clampN(d4.x)], 1);
    atomicAdd(&g_deg[clampN(d4.y)], 1);
    atomicAdd(&g_deg[clampN(d4.z)], 1);
    atomicAdd(&g_deg[clampN(d4.w)], 1);
}

#define SCAN_PER ((N_NODES + 1023) / 1024)    // 49
__global__ void scan_kernel() {
    __shared__ int buf[1024];
    int tid  = threadIdx.x;
    int base = tid * SCAN_PER;
    int lim  = min(base + SCAN_PER, N_NODES);
    int sum = 0;
    for (int i = base; i < lim; ++i) sum += g_deg[i] + 1;   // +1 self loop
    buf[tid] = sum;
    __syncthreads();
    for (int off = 1; off < 1024; off <<= 1) {
        int t = (tid >= off) ? buf[tid - off] : 0;
        __syncthreads();
        buf[tid] += t;
        __syncthreads();
    }
    int run = buf[tid] - sum;
    for (int i = base; i < lim; ++i) {
        g_rowptr[i] = run;
        g_fill[i]   = run;
        run += g_deg[i] + 1;
        g_deg[i] = 0;          // restore for next replay
    }
    if (tid == 1023) g_rowptr[N_NODES] = buf[1023];
}

__global__ void fill_kernel(const int* __restrict__ ei) {
    int i = blockIdx.x * blockDim.x + threadIdx.x;
    if (i < E4) {
        int4 s4 = ((const int4*)ei)[i];
        int4 d4 = ((const int4*)(ei + E_EDGES))[i];
        int p;
        p = atomicAdd(&g_fill[clampN(d4.x)], 1); if (p >= 0 && p < EP) g_esrc[p] = clampN(s4.x);
        p = atomicAdd(&g_fill[clampN(d4.y)], 1); if (p >= 0 && p < EP) g_esrc[p] = clampN(s4.y);
        p = atomicAdd(&g_fill[clampN(d4.z)], 1); if (p >= 0 && p < EP) g_esrc[p] = clampN(s4.z);
        p = atomicAdd(&g_fill[clampN(d4.w)], 1); if (p >= 0 && p < EP) g_esrc[p] = clampN(s4.w);
    } else {
        int n = i - E4;
        if (n < N_NODES) {
            int p = atomicAdd(&g_fill[n], 1);
            if (p >= 0 && p < EP) g_esrc[p] = n;
        }
    }
}

// ---------------- fp16 tensor-core GEMM + fused attention ----------------------
struct SmemAB { __half Ah[64][LDA]; __half Bh[32][LDB]; };
union SmemU { SmemAB ab; float Cs[64][LDC]; };

__global__ void gemm_att_kernel(const float* __restrict__ Aext,
                                const float* __restrict__ B,
                                const float* __restrict__ att_src,
                                const float* __restrict__ att_dst,
                                int use_ext, int M) {
    __shared__ __align__(16) SmemU sh;
    const float* Ap = use_ext ? Aext : (const float*)g_agg4;
    int tid = threadIdx.x;
    int wid = tid >> 5;
    int wm = wid & 3;
    int wn = wid >> 2;
    int bm0 = blockIdx.x * 64;

    wmma::fragment<wmma::accumulator, 16, 16, 16, float> acc[4];
#pragma unroll
    for (int j = 0; j < 4; ++j) wmma::fill_fragment(acc[j], 0.f);

    for (int kt = 0; kt < 4; ++kt) {
#pragma unroll
        for (int t = 0; t < 2; ++t) {
            int id = tid + t * 256;
            int r  = id >> 3;
            int c4 = (id & 7) * 4;
            int gr = bm0 + r;
            float4 v = (gr < M) ? ((const float4*)&Ap[gr * 128 + kt * 32])[c4 >> 2]
                                : make_float4(0.f, 0.f, 0.f, 0.f);
            __half2 lo = __floats2half2_rn(v.x, v.y);
            __half2 hi = __floats2half2_rn(v.z, v.w);
            *(__half2*)&sh.ab.Ah[r][c4]     = lo;
            *(__half2*)&sh.ab.Ah[r][c4 + 2] = hi;
        }
#pragma unroll
        for (int t = 0; t < 4; ++t) {
            int id  = tid + t * 256;
            int row = id >> 5;
            int c4  = (id & 31) * 4;
            float4 v = ((const float4*)&B[(kt * 32 + row) * 128])[c4 >> 2];
            __half2 lo = __floats2half2_rn(v.x, v.y);
            __half2 hi = __floats2half2_rn(v.z, v.w);
            *(__half2*)&sh.ab.Bh[row][c4]     = lo;
            *(__half2*)&sh.ab.Bh[row][c4 + 2] = hi;
        }
        __syncthreads();
#pragma unroll
        for (int ks = 0; ks < 2; ++ks) {
            wmma::fragment<wmma::matrix_a, 16, 16, 16, __half, wmma::row_major> a;
            wmma::load_matrix_sync(a, &sh.ab.Ah[wm * 16][ks * 16], LDA);
#pragma unroll
            for (int j = 0; j < 4; ++j) {
                wmma::fragment<wmma::matrix_b, 16, 16, 16, __half, wmma::row_major> b;
                wmma::load_matrix_sync(b, &sh.ab.Bh[ks * 16][wn * 64 + j * 16], LDB);
                wmma::mma_sync(acc[j], a, b, acc[j]);
            }
        }
        __syncthreads();
    }

#pragma unroll
    for (int j = 0; j < 4; ++j)
        wmma::store_matrix_sync(&sh.Cs[wm * 16][wn * 64 + j * 16], acc[j], LDC,
                                wmma::mem_row_major);
    __syncthreads();

    {
        int r  = tid >> 2;
        int hd = tid & 3;
        int gr = bm0 + r;
        if (gr < M) {
            float s = 0.f, d = 0.f;
#pragma unroll
            for (int i = 0; i < 32; ++i) {
                float v = sh.Cs[r][hd * 32 + i];
                s += v * att_src[hd * 32 + i];
                d += v * att_dst[hd * 32 + i];
            }
            ((float*)g_asrc4)[gr * 4 + hd] = s;
            ((float*)g_adst4)[gr * 4 + hd] = d;
        }
    }

#pragma unroll
    for (int t = 0; t < 4; ++t) {
        int id  = tid + t * 256;
        int row = id >> 4;
        int sl  = id & 15;
        int gr  = bm0 + row;
        if (gr < M) {
            float4 v0 = *(const float4*)&sh.Cs[row][sl * 8];
            float4 v1 = *(const float4*)&sh.Cs[row][sl * 8 + 4];
            __half2 a = __floats2half2_rn(v0.x, v0.y);
            __half2 b = __floats2half2_rn(v0.z, v0.w);
            __half2 c = __floats2half2_rn(v1.x, v1.y);
            __half2 d = __floats2half2_rn(v1.z, v1.w);
            uint4 u;
            u.x = *(unsigned*)&a; u.y = *(unsigned*)&b;
            u.z = *(unsigned*)&c; u.w = *(unsigned*)&d;
            g_h16[gr * 16 + sl] = u;
        }
    }
}

// ---------------- GAT aggregation ------------------------------------------------
// warp/node; half-warp per edge (LDG.128); full chunks specialized (no predicates);
// launch_bounds raises occupancy (issue-bound per ncu R14: fma 30% + alu 31%).
__global__ void __launch_bounds__(256, 5) agg_kernel(const float* __restrict__ bias) {
    __shared__ float4 s_alpha[8][32];
    __shared__ int    s_src[8][33];
    int wband = threadIdx.x >> 5;
    int w = (blockIdx.x * blockDim.x + threadIdx.x) >> 5;
    if (w >= N_NODES) return;
    int lane = threadIdx.x & 31;
    int l16    = lane & 15;
    int half16 = lane >> 4;
    int hd2    = l16 >> 2;
    int beg = g_rowptr[w];
    int end = g_rowptr[w + 1];
    float4 ad = g_adst4[w];

    float4 acc0 = make_float4(0.f, 0.f, 0.f, 0.f);
    float4 acc1 = make_float4(0.f, 0.f, 0.f, 0.f);
    float4 den  = make_float4(0.f, 0.f, 0.f, 0.f);

    // prologue: first chunk
    int    cur_s  = 0;
    float4 cur_as = make_float4(0.f, 0.f, 0.f, 0.f);
    if (beg + lane < end) {
        cur_s  = g_esrc[beg + lane];
        cur_as = g_asrc4[cur_s];
    }

    int j0 = beg;
    // ---- full 32-edge chunks: no per-edge predicates ----
    for (; j0 + 32 <= end; j0 += 32) {
        float4 ex;
        ex.x = __expf(lrelu(cur_as.x + ad.x));
        ex.y = __expf(lrelu(cur_as.y + ad.y));
        ex.z = __expf(lrelu(cur_as.z + ad.z));
        ex.w = __expf(lrelu(cur_as.w + ad.w));
        den.x += ex.x; den.y += ex.y; den.z += ex.z; den.w += ex.w;
        s_alpha[wband][lane] = ex;
        s_src[wband][lane]   = cur_s;
        __syncwarp();

        int nj = j0 + 32;
        int    nxt_s  = 0;
        float4 nxt_as = make_float4(0.f, 0.f, 0.f, 0.f);
        if (nj + lane < end) {
            nxt_s  = g_esrc[nj + lane];
            nxt_as = g_asrc4[nxt_s];
        }

#pragma unroll 8
        for (int t = 0; t < 32; t += 2) {
            float wgt = ((const float*)&s_alpha[wband][t + half16])[hd2];
            int s = s_src[wband][t + half16];
            uint4 u = g_h16[s * 16 + l16];
            float2 f0 = __half22float2(*(__half2*)&u.x);
            float2 f1 = __half22float2(*(__half2*)&u.y);
            float2 f2 = __half22float2(*(__half2*)&u.z);
            float2 f3 = __half22float2(*(__half2*)&u.w);
            acc0.x += f0.x * wgt; acc0.y += f0.y * wgt;
            acc0.z += f1.x * wgt; acc0.w += f1.y * wgt;
            acc1.x += f2.x * wgt; acc1.y += f2.y * wgt;
            acc1.z += f3.x * wgt; acc1.w += f3.y * wgt;
        }
        __syncwarp();
        cur_s = nxt_s; cur_as = nxt_as;
    }

    // ---- tail chunk (< 32 edges) ----
    int cnt = end - j0;
    if (cnt > 0) {
        if (lane < cnt) {
            float4 ex;
            ex.x = __expf(lrelu(cur_as.x + ad.x));
            ex.y = __expf(lrelu(cur_as.y + ad.y));
            ex.z = __expf(lrelu(cur_as.z + ad.z));
            ex.w = __expf(lrelu(cur_as.w + ad.w));
            den.x += ex.x; den.y += ex.y; den.z += ex.z; den.w += ex.w;
            s_alpha[wband][lane] = ex;
            s_src[wband][lane]   = cur_s;
        }
        __syncwarp();
        for (int t = 0; t < cnt; t += 2) {
            int te = t + half16;
            float wgt = 0.f;
            int s = 0;
            if (te < cnt) {
                wgt = ((const float*)&s_alpha[wband][te])[hd2];
                s   = s_src[wband][te];
            }
            uint4 u = g_h16[s * 16 + l16];
            float2 f0 = __half22float2(*(__half2*)&u.x);
            float2 f1 = __half22float2(*(__half2*)&u.y);
            float2 f2 = __half22float2(*(__half2*)&u.z);
            float2 f3 = __half22float2(*(__half2*)&u.w);
            acc0.x += f0.x * wgt; acc0.y += f0.y * wgt;
            acc0.z += f1.x * wgt; acc0.w += f1.y * wgt;
            acc1.x += f2.x * wgt; acc1.y += f2.y * wgt;
            acc1.z += f3.x * wgt; acc1.w += f3.y * wgt;
        }
    }

    // reduce denominators + combine half-pair accumulators
#pragma unroll
    for (int off = 16; off; off >>= 1) {
        den.x += __shfl_xor_sync(0xffffffffu, den.x, off);
        den.y += __shfl_xor_sync(0xffffffffu, den.y, off);
        den.z += __shfl_xor_sync(0xffffffffu, den.z, off);
        den.w += __shfl_xor_sync(0xffffffffu, den.w, off);
    }
    acc0.x += __shfl_xor_sync(0xffffffffu, acc0.x, 16);
    acc0.y += __shfl_xor_sync(0xffffffffu, acc0.y, 16);
    acc0.z += __shfl_xor_sync(0xffffffffu, acc0.z, 16);
    acc0.w += __shfl_xor_sync(0xffffffffu, acc0.w, 16);
    acc1.x += __shfl_xor_sync(0xffffffffu, acc1.x, 16);
    acc1.y += __shfl_xor_sync(0xffffffffu, acc1.y, 16);
    acc1.z += __shfl_xor_sync(0xffffffffu, acc1.z, 16);
    acc1.w += __shfl_xor_sync(0xffffffffu, acc1.w, 16);

    if (half16 == 0) {
        float inv = 1.f / (comp4(den, hd2) + 1e-16f);
        acc0.x *= inv; acc0.y *= inv; acc0.z *= inv; acc0.w *= inv;
        acc1.x *= inv; acc1.y *= inv; acc1.z *= inv; acc1.w *= inv;
        if (bias) {
            const float* bp = bias + l16 * 8;
            float v;
            v = acc0.x + bp[0]; acc0.x = v > 0.f ? v : (__expf(v) - 1.f);
            v = acc0.y + bp[1]; acc0.y = v > 0.f ? v : (__expf(v) - 1.f);
            v = acc0.z + bp[2]; acc0.z = v > 0.f ? v : (__expf(v) - 1.f);
            v = acc0.w + bp[3]; acc0.w = v > 0.f ? v : (__expf(v) - 1.f);
            v = acc1.x + bp[4]; acc1.x = v > 0.f ? v : (__expf(v) - 1.f);
            v = acc1.y + bp[5]; acc1.y = v > 0.f ? v : (__expf(v) - 1.f);
            v = acc1.z + bp[6]; acc1.z = v > 0.f ? v : (__expf(v) - 1.f);
            v = acc1.w + bp[7]; acc1.w = v > 0.f ? v : (__expf(v) - 1.f);
        }
        g_agg4[w * HC4 + l16 * 2]     = acc0;
        g_agg4[w * HC4 + l16 * 2 + 1] = acc1;
    }
}

// ---------------- global mean pool (batch is sorted, int32) --------------------
__global__ void pool_kernel(const int* __restrict__ batch) {
    const float* feats = (const float*)g_agg4;
    int c  = threadIdx.x;
    int n0 = blockIdx.x * 128;
    int n1 = min(n0 + 128, N_NODES);
    if (n0 >= N_NODES) return;
    float acc = 0.f;
    int curg = batch[n0] & (NGRAPH - 1);
    int cnt_local = 0;
    for (int n = n0; n < n1; ++n) {
        int g = batch[n] & (NGRAPH - 1);
        if (g != curg) {
            atomicAdd(&g_pool[curg * HC + c], acc);
            if (c == 0) atomicAdd(&g_cnt[curg], (float)cnt_local);
            acc = 0.f; cnt_local = 0; curg = g;
        }
        acc += feats[n * HC + c];
        cnt_local++;
    }
    atomicAdd(&g_pool[curg * HC + c], acc);
    if (c == 0) atomicAdd(&g_cnt[curg], (float)cnt_local);
}

// ---------------- FC + log_softmax ---------------------------------------------
__global__ void final_kernel(const float* __restrict__ fcW, const float* __restrict__ fcb,
                             const float* __restrict__ b2, float* __restrict__ out) {
    __shared__ float sh[128 * 8 + 8];
    int g = blockIdx.x;
    int c = threadIdx.x;
    float cnt = g_cnt[g];
    float mean = 0.f;
    if (cnt > 0.f) mean = g_pool[g * HC + c] / cnt + b2[c];
#pragma unroll
    for (int j = 0; j < 8; ++j) sh[c * 8 + j] = mean * fcW[c * 8 + j];
    __syncthreads();
    if (c < 8) {
        float s = fcb[c];
        for (int k = 0; k < 128; ++k) s += sh[k * 8 + c];
        sh[1024 + c] = s;
    }
    __syncthreads();
    if (c == 0) {
        float mx = sh[1024];
#pragma unroll
        for (int j = 1; j < 8; ++j) mx = fmaxf(mx, sh[1024 + j]);
        float se = 0.f;
#pragma unroll
        for (int j = 0; j < 8; ++j) se += __expf(sh[1024 + j] - mx);
        float lse = logf(se) + mx;
#pragma unroll
        for (int j = 0; j < 8; ++j) out[g * 8 + j] = sh[1024 + j] - lse;
    }
}

// ---------------- launch --------------------------------------------------------
extern "C" void kernel_launch(void* const* d_in, const int* in_sizes, int n_in,
                              void* d_out, int out_size) {
    const float* x        = (const float*)d_in[0];
    const int*   ei       = (const int*)d_in[1];
    const int*   batch    = (const int*)d_in[2];
    const float* W1       = (const float*)d_in[3];
    const float* att_src1 = (const float*)d_in[4];
    const float* att_dst1 = (const float*)d_in[5];
    const float* b1       = (const float*)d_in[6];
    const float* W2       = (const float*)d_in[7];
    const float* att_src2 = (const float*)d_in[8];
    const float* att_dst2 = (const float*)d_in[9];
    const float* b2       = (const float*)d_in[10];
    const float* fcW      = (const float*)d_in[11];
    const float* fcb      = (const float*)d_in[12];
    float*       out      = (float*)d_out;

    const int GB = (N_NODES + 63) / 64;
    const int FB = (E4 + N_NODES + 255) / 256;

    hist_kernel<<<(E4 + 255) / 256, 256>>>(ei);
    scan_kernel<<<1, 1024>>>();
    gemm_att_kernel<<<GB, 256>>>(x, W1, att_src1, att_dst1, 1, N_NODES);
    fill_kernel<<<FB, 256>>>(ei);
    agg_kernel<<<(N_NODES + 7) / 8, 256>>>(b1);

    gemm_att_kernel<<<GB, 256>>>(nullptr, W2, att_src2, att_dst2, 0, N_NODES);
    agg_kernel<<<(N_NODES + 7) / 8, 256>>>(nullptr);

    zero_pool_kernel<<<(NGRAPH * HC + 255) / 256, 256>>>();
    pool_kernel<<<(N_NODES + 127) / 128, 128>>>(batch);
    final_kernel<<<NGRAPH, 128>>>(fcW, fcb, b2, out);
}

// round 16
// speedup vs baseline: 1.0808x; 1.0802x over previous
#include <cuda_runtime.h>
#include <cuda_fp16.h>
#include <mma.h>
#include <math.h>

using namespace nvcuda;

#define N_NODES   50000
#define E_EDGES   1600000
#define E4        (E_EDGES / 4)
#define EP        (E_EDGES + N_NODES)
#define NHEADS    4
#define HC        128
#define HC4       32
#define NGRAPH    64

#define LDA 40
#define LDB 136
#define LDC 132

// ---------------- scratch ------------------------------------------------------
__device__ uint4  g_h16[N_NODES * 16];    // transformed features, fp16x8 per slot
__device__ float4 g_agg4[N_NODES * HC4];  // aggregation output (fp32)
__device__ float4 g_asrc4[N_NODES];
__device__ float4 g_adst4[N_NODES];
__device__ int    g_deg[N_NODES];
__device__ int    g_rowptr[N_NODES + 1];
__device__ int    g_fill[N_NODES];
__device__ int    g_esrc[EP];
__device__ float  g_pool[NGRAPH * HC];
__device__ float  g_cnt[NGRAPH];

// ---------------- helpers ------------------------------------------------------
__device__ __forceinline__ float lrelu(float v) { return v > 0.f ? v : 0.2f * v; }
__device__ __forceinline__ float comp4(float4 v, int i) {
    return i == 0 ? v.x : (i == 1 ? v.y : (i == 2 ? v.z : v.w));
}
__device__ __forceinline__ int clampN(int v) {
    return v < 0 ? 0 : (v >= N_NODES ? N_NODES - 1 : v);
}

// ---------------- zero scratch ---------------------------------------------------
__global__ void zero_deg_kernel() {
    int i = blockIdx.x * blockDim.x + threadIdx.x;
    if (i < N_NODES) g_deg[i] = 0;
}

__global__ void zero_pool_kernel() {
    int i = blockIdx.x * blockDim.x + threadIdx.x;
    if (i < NGRAPH * HC) g_pool[i] = 0.f;
    if (i < NGRAPH) g_cnt[i] = 0.f;
}

// ---------------- build CSR (counting sort by dst) -----------------------------
__global__ void hist_kernel(const int* __restrict__ ei) {
    int i = blockIdx.x * blockDim.x + threadIdx.x;
    if (i >= E4) return;
    int4 d4 = ((const int4*)(ei + E_EDGES))[i];
    atomicAdd(&g_deg[clampN(d4.x)], 1);
    atomicAdd(&g_deg[clampN(d4.y)], 1);
    atomicAdd(&g_deg[clampN(d4.z)], 1);
    atomicAdd(&g_deg[clampN(d4.w)], 1);
}

#define SCAN_PER ((N_NODES + 1023) / 1024)    // 49
__global__ void scan_kernel() {
    __shared__ int buf[1024];
    int tid  = threadIdx.x;
    int base = tid * SCAN_PER;
    int lim  = min(base + SCAN_PER, N_NODES);
    int sum = 0;
    for (int i = base; i < lim; ++i) sum += g_deg[i] + 1;   // +1 self loop
    buf[tid] = sum;
    __syncthreads();
    for (int off = 1; off < 1024; off <<= 1) {
        int t = (tid >= off) ? buf[tid - off] : 0;
        __syncthreads();
        buf[tid] += t;
        __syncthreads();
    }
    int run = buf[tid] - sum;
    for (int i = base; i < lim; ++i) {
        g_rowptr[i] = run;
        g_fill[i]   = run;
        run += g_deg[i] + 1;
    }
    if (tid == 1023) g_rowptr[N_NODES] = buf[1023];
}

__global__ void fill_kernel(const int* __restrict__ ei) {
    int i = blockIdx.x * blockDim.x + threadIdx.x;
    if (i < E4) {
        int4 s4 = ((const int4*)ei)[i];
        int4 d4 = ((const int4*)(ei + E_EDGES))[i];
        int p;
        p = atomicAdd(&g_fill[clampN(d4.x)], 1); if (p >= 0 && p < EP) g_esrc[p] = clampN(s4.x);
        p = atomicAdd(&g_fill[clampN(d4.y)], 1); if (p >= 0 && p < EP) g_esrc[p] = clampN(s4.y);
        p = atomicAdd(&g_fill[clampN(d4.z)], 1); if (p >= 0 && p < EP) g_esrc[p] = clampN(s4.z);
        p = atomicAdd(&g_fill[clampN(d4.w)], 1); if (p >= 0 && p < EP) g_esrc[p] = clampN(s4.w);
    } else {
        int n = i - E4;
        if (n < N_NODES) {
            int p = atomicAdd(&g_fill[n], 1);
            if (p >= 0 && p < EP) g_esrc[p] = n;
        }
    }
}

// ---------------- fp16 tensor-core GEMM + fused attention ----------------------
struct SmemAB { __half Ah[64][LDA]; __half Bh[32][LDB]; };
union SmemU { SmemAB ab; float Cs[64][LDC]; };

__global__ void gemm_att_kernel(const float* __restrict__ Aext,
                                const float* __restrict__ B,
                                const float* __restrict__ att_src,
                                const float* __restrict__ att_dst,
                                int use_ext, int M) {
    __shared__ __align__(16) SmemU sh;
    const float* Ap = use_ext ? Aext : (const float*)g_agg4;
    int tid = threadIdx.x;
    int wid = tid >> 5;
    int wm = wid & 3;
    int wn = wid >> 2;
    int bm0 = blockIdx.x * 64;

    wmma::fragment<wmma::accumulator, 16, 16, 16, float> acc[4];
#pragma unroll
    for (int j = 0; j < 4; ++j) wmma::fill_fragment(acc[j], 0.f);

    for (int kt = 0; kt < 4; ++kt) {
#pragma unroll
        for (int t = 0; t < 2; ++t) {
            int id = tid + t * 256;
            int r  = id >> 3;
            int c4 = (id & 7) * 4;
            int gr = bm0 + r;
            float4 v = (gr < M) ? ((const float4*)&Ap[gr * 128 + kt * 32])[c4 >> 2]
                                : make_float4(0.f, 0.f, 0.f, 0.f);
            __half2 lo = __floats2half2_rn(v.x, v.y);
            __half2 hi = __floats2half2_rn(v.z, v.w);
            *(__half2*)&sh.ab.Ah[r][c4]     = lo;
            *(__half2*)&sh.ab.Ah[r][c4 + 2] = hi;
        }
#pragma unroll
        for (int t = 0; t < 4; ++t) {
            int id  = tid + t * 256;
            int row = id >> 5;
            int c4  = (id & 31) * 4;
            float4 v = ((const float4*)&B[(kt * 32 + row) * 128])[c4 >> 2];
            __half2 lo = __floats2half2_rn(v.x, v.y);
            __half2 hi = __floats2half2_rn(v.z, v.w);
            *(__half2*)&sh.ab.Bh[row][c4]     = lo;
            *(__half2*)&sh.ab.Bh[row][c4 + 2] = hi;
        }
        __syncthreads();
#pragma unroll
        for (int ks = 0; ks < 2; ++ks) {
            wmma::fragment<wmma::matrix_a, 16, 16, 16, __half, wmma::row_major> a;
            wmma::load_matrix_sync(a, &sh.ab.Ah[wm * 16][ks * 16], LDA);
#pragma unroll
            for (int j = 0; j < 4; ++j) {
                wmma::fragment<wmma::matrix_b, 16, 16, 16, __half, wmma::row_major> b;
                wmma::load_matrix_sync(b, &sh.ab.Bh[ks * 16][wn * 64 + j * 16], LDB);
                wmma::mma_sync(acc[j], a, b, acc[j]);
            }
        }
        __syncthreads();
    }

#pragma unroll
    for (int j = 0; j < 4; ++j)
        wmma::store_matrix_sync(&sh.Cs[wm * 16][wn * 64 + j * 16], acc[j], LDC,
                                wmma::mem_row_major);
    __syncthreads();

    {
        int r  = tid >> 2;
        int hd = tid & 3;
        int gr = bm0 + r;
        if (gr < M) {
            float s = 0.f, d = 0.f;
#pragma unroll
            for (int i = 0; i < 32; ++i) {
                float v = sh.Cs[r][hd * 32 + i];
                s += v * att_src[hd * 32 + i];
                d += v * att_dst[hd * 32 + i];
            }
            ((float*)g_asrc4)[gr * 4 + hd] = s;
            ((float*)g_adst4)[gr * 4 + hd] = d;
        }
    }

#pragma unroll
    for (int t = 0; t < 4; ++t) {
        int id  = tid + t * 256;
        int row = id >> 4;
        int sl  = id & 15;
        int gr  = bm0 + row;
        if (gr < M) {
            float4 v0 = *(const float4*)&sh.Cs[row][sl * 8];
            float4 v1 = *(const float4*)&sh.Cs[row][sl * 8 + 4];
            __half2 a = __floats2half2_rn(v0.x, v0.y);
            __half2 b = __floats2half2_rn(v0.z, v0.w);
            __half2 c = __floats2half2_rn(v1.x, v1.y);
            __half2 d = __floats2half2_rn(v1.z, v1.w);
            uint4 u;
            u.x = *(unsigned*)&a; u.y = *(unsigned*)&b;
            u.z = *(unsigned*)&c; u.w = *(unsigned*)&d;
            g_h16[gr * 16 + sl] = u;
        }
    }
}

// ---------------- GAT aggregation: R13 structure + fp16 HFMA2 accumulation -----
// warp/node; half-warp per edge (LDG.128); alpha stored per-head as half in smem;
// inner loop: LDS.U16 + broadcast + 4x HFMA2 (issue-bound fix per R14 profile).
__global__ void agg_kernel(const float* __restrict__ bias) {
    __shared__ __half s_ah[8][32][4];   // [warp][edge][head] unnormalized alpha
    __shared__ int    s_src[8][33];
    int wband = threadIdx.x >> 5;
    int w = (blockIdx.x * blockDim.x + threadIdx.x) >> 5;
    if (w >= N_NODES) return;
    int lane = threadIdx.x & 31;
    int l16    = lane & 15;
    int half16 = lane >> 4;
    int hd2    = l16 >> 2;
    int beg = g_rowptr[w];
    int end = g_rowptr[w + 1];
    float4 ad = g_adst4[w];

    __half2 h0 = __float2half2_rn(0.f), h1 = h0, h2 = h0, h3 = h0;
    float4 den = make_float4(0.f, 0.f, 0.f, 0.f);

    // prologue: first chunk
    int    cur_s  = 0;
    float4 cur_as = make_float4(0.f, 0.f, 0.f, 0.f);
    if (beg + lane < end) {
        cur_s  = g_esrc[beg + lane];
        cur_as = g_asrc4[cur_s];
    }

    for (int j0 = beg; j0 < end; j0 += 32) {
        int cnt = min(32, end - j0);
        if (lane < cnt) {
            float4 ex;
            ex.x = __expf(lrelu(cur_as.x + ad.x));
            ex.y = __expf(lrelu(cur_as.y + ad.y));
            ex.z = __expf(lrelu(cur_as.z + ad.z));
            ex.w = __expf(lrelu(cur_as.w + ad.w));
            den.x += ex.x; den.y += ex.y; den.z += ex.z; den.w += ex.w;
            __half2 p01 = __floats2half2_rn(ex.x, ex.y);
            __half2 p23 = __floats2half2_rn(ex.z, ex.w);
            uint2 pu;
            pu.x = *(unsigned*)&p01;
            pu.y = *(unsigned*)&p23;
            *(uint2*)&s_ah[wband][lane][0] = pu;
            s_src[wband][lane] = cur_s;
        }
        __syncwarp();

        // prefetch next chunk
        int nj = j0 + 32;
        int    nxt_s  = 0;
        float4 nxt_as = make_float4(0.f, 0.f, 0.f, 0.f);
        if (nj + lane < end) {
            nxt_s  = g_esrc[nj + lane];
            nxt_as = g_asrc4[nxt_s];
        }

        // gather: 2 edges per iteration, 4 HFMA2 per edge-row segment
#pragma unroll 4
        for (int t = 0; t < cnt; t += 2) {
            int te = t + half16;
            __half2 wgt2 = __float2half2_rn(0.f);
            int s = 0;
            if (te < cnt) {
                wgt2 = __half2half2(s_ah[wband][te][hd2]);
                s    = s_src[wband][te];
            }
            uint4 u = g_h16[s * 16 + l16];
            h0 = __hfma2(*(__half2*)&u.x, wgt2, h0);
            h1 = __hfma2(*(__half2*)&u.y, wgt2, h1);
            h2 = __hfma2(*(__half2*)&u.z, wgt2, h2);
            h3 = __hfma2(*(__half2*)&u.w, wgt2, h3);
        }
        __syncwarp();
        cur_s = nxt_s; cur_as = nxt_as;
    }

    // convert to fp32 for reduction/normalization
    float2 f0 = __half22float2(h0);
    float2 f1 = __half22float2(h1);
    float2 f2 = __half22float2(h2);
    float2 f3 = __half22float2(h3);
    float4 acc0 = make_float4(f0.x, f0.y, f1.x, f1.y);
    float4 acc1 = make_float4(f2.x, f2.y, f3.x, f3.y);

#pragma unroll
    for (int off = 16; off; off >>= 1) {
        den.x += __shfl_xor_sync(0xffffffffu, den.x, off);
        den.y += __shfl_xor_sync(0xffffffffu, den.y, off);
        den.z += __shfl_xor_sync(0xffffffffu, den.z, off);
        den.w += __shfl_xor_sync(0xffffffffu, den.w, off);
    }
    acc0.x += __shfl_xor_sync(0xffffffffu, acc0.x, 16);
    acc0.y += __shfl_xor_sync(0xffffffffu, acc0.y, 16);
    acc0.z += __shfl_xor_sync(0xffffffffu, acc0.z, 16);
    acc0.w += __shfl_xor_sync(0xffffffffu, acc0.w, 16);
    acc1.x += __shfl_xor_sync(0xffffffffu, acc1.x, 16);
    acc1.y += __shfl_xor_sync(0xffffffffu, acc1.y, 16);
    acc1.z += __shfl_xor_sync(0xffffffffu, acc1.z, 16);
    acc1.w += __shfl_xor_sync(0xffffffffu, acc1.w, 16);

    if (half16 == 0) {
        float inv = 1.f / (comp4(den, hd2) + 1e-16f);
        acc0.x *= inv; acc0.y *= inv; acc0.z *= inv; acc0.w *= inv;
        acc1.x *= inv; acc1.y *= inv; acc1.z *= inv; acc1.w *= inv;
        if (bias) {
            const float* bp = bias + l16 * 8;
            float v;
            v = acc0.x + bp[0]; acc0.x = v > 0.f ? v : (__expf(v) - 1.f);
            v = acc0.y + bp[1]; acc0.y = v > 0.f ? v : (__expf(v) - 1.f);
            v = acc0.z + bp[2]; acc0.z = v > 0.f ? v : (__expf(v) - 1.f);
            v = acc0.w + bp[3]; acc0.w = v > 0.f ? v : (__expf(v) - 1.f);
            v = acc1.x + bp[4]; acc1.x = v > 0.f ? v : (__expf(v) - 1.f);
            v = acc1.y + bp[5]; acc1.y = v > 0.f ? v : (__expf(v) - 1.f);
            v = acc1.z + bp[6]; acc1.z = v > 0.f ? v : (__expf(v) - 1.f);
            v = acc1.w + bp[7]; acc1.w = v > 0.f ? v : (__expf(v) - 1.f);
        }
        g_agg4[w * HC4 + l16 * 2]     = acc0;
        g_agg4[w * HC4 + l16 * 2 + 1] = acc1;
    }
}

// ---------------- global mean pool (batch is sorted, int32) --------------------
__global__ void pool_kernel(const int* __restrict__ batch) {
    const float* feats = (const float*)g_agg4;
    int c  = threadIdx.x;
    int n0 = blockIdx.x * 128;
    int n1 = min(n0 + 128, N_NODES);
    if (n0 >= N_NODES) return;
    float acc = 0.f;
    int curg = batch[n0] & (NGRAPH - 1);
    int cnt_local = 0;
    for (int n = n0; n < n1; ++n) {
        int g = batch[n] & (NGRAPH - 1);
        if (g != curg) {
            atomicAdd(&g_pool[curg * HC + c], acc);
            if (c == 0) atomicAdd(&g_cnt[curg], (float)cnt_local);
            acc = 0.f; cnt_local = 0; curg = g;
        }
        acc += feats[n * HC + c];
        cnt_local++;
    }
    atomicAdd(&g_pool[curg * HC + c], acc);
    if (c == 0) atomicAdd(&g_cnt[curg], (float)cnt_local);
}

// ---------------- FC + log_softmax ---------------------------------------------
__global__ void final_kernel(const float* __restrict__ fcW, const float* __restrict__ fcb,
                             const float* __restrict__ b2, float* __restrict__ out) {
    __shared__ float sh[128 * 8 + 8];
    int g = blockIdx.x;
    int c = threadIdx.x;
    float cnt = g_cnt[g];
    float mean = 0.f;
    if (cnt > 0.f) mean = g_pool[g * HC + c] / cnt + b2[c];
#pragma unroll
    for (int j = 0; j < 8; ++j) sh[c * 8 + j] = mean * fcW[c * 8 + j];
    __syncthreads();
    if (c < 8) {
        float s = fcb[c];
        for (int k = 0; k < 128; ++k) s += sh[k * 8 + c];
        sh[1024 + c] = s;
    }
    __syncthreads();
    if (c == 0) {
        float mx = sh[1024];
#pragma unroll
        for (int j = 1; j < 8; ++j) mx = fmaxf(mx, sh[1024 + j]);
        float se = 0.f;
#pragma unroll
        for (int j = 0; j < 8; ++j) se += __expf(sh[1024 + j] - mx);
        float lse = logf(se) + mx;
#pragma unroll
        for (int j = 0; j < 8; ++j) out[g * 8 + j] = sh[1024 + j] - lse;
    }
}

// ---------------- launch --------------------------------------------------------
extern "C" void kernel_launch(void* const* d_in, const int* in_sizes, int n_in,
                              void* d_out, int out_size) {
    const float* x        = (const float*)d_in[0];
    const int*   ei       = (const int*)d_in[1];
    const int*   batch    = (const int*)d_in[2];
    const float* W1       = (const float*)d_in[3];
    const float* att_src1 = (const float*)d_in[4];
    const float* att_dst1 = (const float*)d_in[5];
    const float* b1       = (const float*)d_in[6];
    const float* W2       = (const float*)d_in[7];
    const float* att_src2 = (const float*)d_in[8];
    const float* att_dst2 = (const float*)d_in[9];
    const float* b2       = (const float*)d_in[10];
    const float* fcW      = (const float*)d_in[11];
    const float* fcb      = (const float*)d_in[12];
    float*       out      = (float*)d_out;

    const int GB = (N_NODES + 63) / 64;
    const int FB = (E4 + N_NODES + 255) / 256;

    zero_deg_kernel<<<(N_NODES + 255) / 256, 256>>>();
    hist_kernel<<<(E4 + 255) / 256, 256>>>(ei);
    scan_kernel<<<1, 1024>>>();
    gemm_att_kernel<<<GB, 256>>>(x, W1, att_src1, att_dst1, 1, N_NODES);
    fill_kernel<<<FB, 256>>>(ei);
    agg_kernel<<<(N_NODES + 7) / 8, 256>>>(b1);

    gemm_att_kernel<<<GB, 256>>>(nullptr, W2, att_src2, att_dst2, 0, N_NODES);
    agg_kernel<<<(N_NODES + 7) / 8, 256>>>(nullptr);

    zero_pool_kernel<<<(NGRAPH * HC + 255) / 256, 256>>>();
    pool_kernel<<<(N_NODES + 127) / 128, 128>>>(batch);
    final_kernel<<<NGRAPH, 128>>>(fcW, fcb, b2, out);
}

// round 17
// speedup vs baseline: 1.1116x; 1.0285x over previous
#include <cuda_runtime.h>
#include <cuda_fp16.h>
#include <mma.h>
#include <math.h>

using namespace nvcuda;

#define N_NODES   50000
#define E_EDGES   1600000
#define E4        (E_EDGES / 4)
#define EP        (E_EDGES + N_NODES)
#define NHEADS    4
#define HC        128
#define HC4       32
#define NGRAPH    64

#define LDA 40
#define LDB 136
#define LDC 132

// ---------------- scratch ------------------------------------------------------
__device__ uint4  g_h16[N_NODES * 16];    // transformed features, fp16x8 per slot
__device__ float4 g_agg4[N_NODES * HC4];  // aggregation output (fp32)
__device__ float4 g_asrc4[N_NODES];
__device__ float4 g_adst4[N_NODES];
__device__ int    g_deg[N_NODES];
__device__ int    g_rowptr[N_NODES + 1];
__device__ int    g_fill[N_NODES];
__device__ int    g_esrc[EP];
__device__ float  g_pool[NGRAPH * HC];
__device__ float  g_cnt[NGRAPH];

// ---------------- side stream (created at image load; no mem delta in-run) -----
struct SideStream {
    cudaStream_t s;
    cudaEvent_t  e_fork, e_join;
    SideStream() {
        cudaStreamCreateWithFlags(&s, cudaStreamNonBlocking);
        cudaEventCreateWithFlags(&e_fork, cudaEventDisableTiming);
        cudaEventCreateWithFlags(&e_join, cudaEventDisableTiming);
    }
};
static SideStream g_side;

// ---------------- helpers ------------------------------------------------------
__device__ __forceinline__ float lrelu(float v) { return v > 0.f ? v : 0.2f * v; }
__device__ __forceinline__ float comp4(float4 v, int i) {
    return i == 0 ? v.x : (i == 1 ? v.y : (i == 2 ? v.z : v.w));
}
__device__ __forceinline__ int clampN(int v) {
    return v < 0 ? 0 : (v >= N_NODES ? N_NODES - 1 : v);
}

// ---------------- zero scratch ---------------------------------------------------
__global__ void zero_deg_kernel() {
    int i = blockIdx.x * blockDim.x + threadIdx.x;
    if (i < N_NODES) g_deg[i] = 0;
}

__global__ void zero_pool_kernel() {
    int i = blockIdx.x * blockDim.x + threadIdx.x;
    if (i < NGRAPH * HC) g_pool[i] = 0.f;
    if (i < NGRAPH) g_cnt[i] = 0.f;
}

// ---------------- build CSR (counting sort by dst) -----------------------------
__global__ void hist_kernel(const int* __restrict__ ei) {
    int i = blockIdx.x * blockDim.x + threadIdx.x;
    if (i >= E4) return;
    int4 d4 = ((const int4*)(ei + E_EDGES))[i];
    atomicAdd(&g_deg[clampN(d4.x)], 1);
    atomicAdd(&g_deg[clampN(d4.y)], 1);
    atomicAdd(&g_deg[clampN(d4.z)], 1);
    atomicAdd(&g_deg[clampN(d4.w)], 1);
}

#define SCAN_PER ((N_NODES + 1023) / 1024)    // 49
__global__ void scan_kernel() {
    __shared__ int buf[1024];
    int tid  = threadIdx.x;
    int base = tid * SCAN_PER;
    int lim  = min(base + SCAN_PER, N_NODES);
    int sum = 0;
    for (int i = base; i < lim; ++i) sum += g_deg[i] + 1;   // +1 self loop
    buf[tid] = sum;
    __syncthreads();
    for (int off = 1; off < 1024; off <<= 1) {
        int t = (tid >= off) ? buf[tid - off] : 0;
        __syncthreads();
        buf[tid] += t;
        __syncthreads();
    }
    int run = buf[tid] - sum;
    for (int i = base; i < lim; ++i) {
        g_rowptr[i] = run;
        g_fill[i]   = run;
        run += g_deg[i] + 1;
    }
    if (tid == 1023) g_rowptr[N_NODES] = buf[1023];
}

__global__ void fill_kernel(const int* __restrict__ ei) {
    int i = blockIdx.x * blockDim.x + threadIdx.x;
    if (i < E4) {
        int4 s4 = ((const int4*)ei)[i];
        int4 d4 = ((const int4*)(ei + E_EDGES))[i];
        int p;
        p = atomicAdd(&g_fill[clampN(d4.x)], 1); if (p >= 0 && p < EP) g_esrc[p] = clampN(s4.x);
        p = atomicAdd(&g_fill[clampN(d4.y)], 1); if (p >= 0 && p < EP) g_esrc[p] = clampN(s4.y);
        p = atomicAdd(&g_fill[clampN(d4.z)], 1); if (p >= 0 && p < EP) g_esrc[p] = clampN(s4.z);
        p = atomicAdd(&g_fill[clampN(d4.w)], 1); if (p >= 0 && p < EP) g_esrc[p] = clampN(s4.w);
    } else {
        int n = i - E4;
        if (n < N_NODES) {
            int p = atomicAdd(&g_fill[n], 1);
            if (p >= 0 && p < EP) g_esrc[p] = n;
        }
    }
}

// ---------------- fp16 tensor-core GEMM + fused attention ----------------------
struct SmemAB { __half Ah[64][LDA]; __half Bh[32][LDB]; };
union SmemU { SmemAB ab; float Cs[64][LDC]; };

__global__ void gemm_att_kernel(const float* __restrict__ Aext,
                                const float* __restrict__ B,
                                const float* __restrict__ att_src,
                                const float* __restrict__ att_dst,
                                int use_ext, int M) {
    __shared__ __align__(16) SmemU sh;
    const float* Ap = use_ext ? Aext : (const float*)g_agg4;
    int tid = threadIdx.x;
    int wid = tid >> 5;
    int wm = wid & 3;
    int wn = wid >> 2;
    int bm0 = blockIdx.x * 64;

    wmma::fragment<wmma::accumulator, 16, 16, 16, float> acc[4];
#pragma unroll
    for (int j = 0; j < 4; ++j) wmma::fill_fragment(acc[j], 0.f);

    for (int kt = 0; kt < 4; ++kt) {
#pragma unroll
        for (int t = 0; t < 2; ++t) {
            int id = tid + t * 256;
            int r  = id >> 3;
            int c4 = (id & 7) * 4;
            int gr = bm0 + r;
            float4 v = (gr < M) ? ((const float4*)&Ap[gr * 128 + kt * 32])[c4 >> 2]
                                : make_float4(0.f, 0.f, 0.f, 0.f);
            __half2 lo = __floats2half2_rn(v.x, v.y);
            __half2 hi = __floats2half2_rn(v.z, v.w);
            *(__half2*)&sh.ab.Ah[r][c4]     = lo;
            *(__half2*)&sh.ab.Ah[r][c4 + 2] = hi;
        }
#pragma unroll
        for (int t = 0; t < 4; ++t) {
            int id  = tid + t * 256;
            int row = id >> 5;
            int c4  = (id & 31) * 4;
            float4 v = ((const float4*)&B[(kt * 32 + row) * 128])[c4 >> 2];
            __half2 lo = __floats2half2_rn(v.x, v.y);
            __half2 hi = __floats2half2_rn(v.z, v.w);
            *(__half2*)&sh.ab.Bh[row][c4]     = lo;
            *(__half2*)&sh.ab.Bh[row][c4 + 2] = hi;
        }
        __syncthreads();
#pragma unroll
        for (int ks = 0; ks < 2; ++ks) {
            wmma::fragment<wmma::matrix_a, 16, 16, 16, __half, wmma::row_major> a;
            wmma::load_matrix_sync(a, &sh.ab.Ah[wm * 16][ks * 16], LDA);
#pragma unroll
            for (int j = 0; j < 4; ++j) {
                wmma::fragment<wmma::matrix_b, 16, 16, 16, __half, wmma::row_major> b;
                wmma::load_matrix_sync(b, &sh.ab.Bh[ks * 16][wn * 64 + j * 16], LDB);
                wmma::mma_sync(acc[j], a, b, acc[j]);
            }
        }
        __syncthreads();
    }

#pragma unroll
    for (int j = 0; j < 4; ++j)
        wmma::store_matrix_sync(&sh.Cs[wm * 16][wn * 64 + j * 16], acc[j], LDC,
                                wmma::mem_row_major);
    __syncthreads();

    {
        int r  = tid >> 2;
        int hd = tid & 3;
        int gr = bm0 + r;
        if (gr < M) {
            float s = 0.f, d = 0.f;
#pragma unroll
            for (int i = 0; i < 32; ++i) {
                float v = sh.Cs[r][hd * 32 + i];
                s += v * att_src[hd * 32 + i];
                d += v * att_dst[hd * 32 + i];
            }
            ((float*)g_asrc4)[gr * 4 + hd] = s;
            ((float*)g_adst4)[gr * 4 + hd] = d;
        }
    }

#pragma unroll
    for (int t = 0; t < 4; ++t) {
        int id  = tid + t * 256;
        int row = id >> 4;
        int sl  = id & 15;
        int gr  = bm0 + row;
        if (gr < M) {
            float4 v0 = *(const float4*)&sh.Cs[row][sl * 8];
            float4 v1 = *(const float4*)&sh.Cs[row][sl * 8 + 4];
            __half2 a = __floats2half2_rn(v0.x, v0.y);
            __half2 b = __floats2half2_rn(v0.z, v0.w);
            __half2 c = __floats2half2_rn(v1.x, v1.y);
            __half2 d = __floats2half2_rn(v1.z, v1.w);
            uint4 u;
            u.x = *(unsigned*)&a; u.y = *(unsigned*)&b;
            u.z = *(unsigned*)&c; u.w = *(unsigned*)&d;
            g_h16[gr * 16 + sl] = u;
        }
    }
}

// ---------------- GAT aggregation: HFMA2 accumulation (R16 best) ---------------
__global__ void agg_kernel(const float* __restrict__ bias) {
    __shared__ __half s_ah[8][32][4];   // [warp][edge][head] unnormalized alpha
    __shared__ int    s_src[8][33];
    int wband = threadIdx.x >> 5;
    int w = (blockIdx.x * blockDim.x + threadIdx.x) >> 5;
    if (w >= N_NODES) return;
    int lane = threadIdx.x & 31;
    int l16    = lane & 15;
    int half16 = lane >> 4;
    int hd2    = l16 >> 2;
    int beg = g_rowptr[w];
    int end = g_rowptr[w + 1];
    float4 ad = g_adst4[w];

    __half2 h0 = __float2half2_rn(0.f), h1 = h0, h2 = h0, h3 = h0;
    float4 den = make_float4(0.f, 0.f, 0.f, 0.f);

    int    cur_s  = 0;
    float4 cur_as = make_float4(0.f, 0.f, 0.f, 0.f);
    if (beg + lane < end) {
        cur_s  = g_esrc[beg + lane];
        cur_as = g_asrc4[cur_s];
    }

    for (int j0 = beg; j0 < end; j0 += 32) {
        int cnt = min(32, end - j0);
        if (lane < cnt) {
            float4 ex;
            ex.x = __expf(lrelu(cur_as.x + ad.x));
            ex.y = __expf(lrelu(cur_as.y + ad.y));
            ex.z = __expf(lrelu(cur_as.z + ad.z));
            ex.w = __expf(lrelu(cur_as.w + ad.w));
            den.x += ex.x; den.y += ex.y; den.z += ex.z; den.w += ex.w;
            __half2 p01 = __floats2half2_rn(ex.x, ex.y);
            __half2 p23 = __floats2half2_rn(ex.z, ex.w);
            uint2 pu;
            pu.x = *(unsigned*)&p01;
            pu.y = *(unsigned*)&p23;
            *(uint2*)&s_ah[wband][lane][0] = pu;
            s_src[wband][lane] = cur_s;
        }
        __syncwarp();

        int nj = j0 + 32;
        int    nxt_s  = 0;
        float4 nxt_as = make_float4(0.f, 0.f, 0.f, 0.f);
        if (nj + lane < end) {
            nxt_s  = g_esrc[nj + lane];
            nxt_as = g_asrc4[nxt_s];
        }

#pragma unroll 4
        for (int t = 0; t < cnt; t += 2) {
            int te = t + half16;
            __half2 wgt2 = __float2half2_rn(0.f);
            int s = 0;
            if (te < cnt) {
                wgt2 = __half2half2(s_ah[wband][te][hd2]);
                s    = s_src[wband][te];
            }
            uint4 u = g_h16[s * 16 + l16];
            h0 = __hfma2(*(__half2*)&u.x, wgt2, h0);
            h1 = __hfma2(*(__half2*)&u.y, wgt2, h1);
            h2 = __hfma2(*(__half2*)&u.z, wgt2, h2);
            h3 = __hfma2(*(__half2*)&u.w, wgt2, h3);
        }
        __syncwarp();
        cur_s = nxt_s; cur_as = nxt_as;
    }

    float2 f0 = __half22float2(h0);
    float2 f1 = __half22float2(h1);
    float2 f2 = __half22float2(h2);
    float2 f3 = __half22float2(h3);
    float4 acc0 = make_float4(f0.x, f0.y, f1.x, f1.y);
    float4 acc1 = make_float4(f2.x, f2.y, f3.x, f3.y);

#pragma unroll
    for (int off = 16; off; off >>= 1) {
        den.x += __shfl_xor_sync(0xffffffffu, den.x, off);
        den.y += __shfl_xor_sync(0xffffffffu, den.y, off);
        den.z += __shfl_xor_sync(0xffffffffu, den.z, off);
        den.w += __shfl_xor_sync(0xffffffffu, den.w, off);
    }
    acc0.x += __shfl_xor_sync(0xffffffffu, acc0.x, 16);
    acc0.y += __shfl_xor_sync(0xffffffffu, acc0.y, 16);
    acc0.z += __shfl_xor_sync(0xffffffffu, acc0.z, 16);
    acc0.w += __shfl_xor_sync(0xffffffffu, acc0.w, 16);
    acc1.x += __shfl_xor_sync(0xffffffffu, acc1.x, 16);
    acc1.y += __shfl_xor_sync(0xffffffffu, acc1.y, 16);
    acc1.z += __shfl_xor_sync(0xffffffffu, acc1.z, 16);
    acc1.w += __shfl_xor_sync(0xffffffffu, acc1.w, 16);

    if (half16 == 0) {
        float inv = 1.f / (comp4(den, hd2) + 1e-16f);
        acc0.x *= inv; acc0.y *= inv; acc0.z *= inv; acc0.w *= inv;
        acc1.x *= inv; acc1.y *= inv; acc1.z *= inv; acc1.w *= inv;
        if (bias) {
            const float* bp = bias + l16 * 8;
            float v;
            v = acc0.x + bp[0]; acc0.x = v > 0.f ? v : (__expf(v) - 1.f);
            v = acc0.y + bp[1]; acc0.y = v > 0.f ? v : (__expf(v) - 1.f);
            v = acc0.z + bp[2]; acc0.z = v > 0.f ? v : (__expf(v) - 1.f);
            v = acc0.w + bp[3]; acc0.w = v > 0.f ? v : (__expf(v) - 1.f);
            v = acc1.x + bp[4]; acc1.x = v > 0.f ? v : (__expf(v) - 1.f);
            v = acc1.y + bp[5]; acc1.y = v > 0.f ? v : (__expf(v) - 1.f);
            v = acc1.z + bp[6]; acc1.z = v > 0.f ? v : (__expf(v) - 1.f);
            v = acc1.w + bp[7]; acc1.w = v > 0.f ? v : (__expf(v) - 1.f);
        }
        g_agg4[w * HC4 + l16 * 2]     = acc0;
        g_agg4[w * HC4 + l16 * 2 + 1] = acc1;
    }
}

// ---------------- global mean pool (batch is sorted, int32) --------------------
__global__ void pool_kernel(const int* __restrict__ batch) {
    const float* feats = (const float*)g_agg4;
    int c  = threadIdx.x;
    int n0 = blockIdx.x * 128;
    int n1 = min(n0 + 128, N_NODES);
    if (n0 >= N_NODES) return;
    float acc = 0.f;
    int curg = batch[n0] & (NGRAPH - 1);
    int cnt_local = 0;
    for (int n = n0; n < n1; ++n) {
        int g = batch[n] & (NGRAPH - 1);
        if (g != curg) {
            atomicAdd(&g_pool[curg * HC + c], acc);
            if (c == 0) atomicAdd(&g_cnt[curg], (float)cnt_local);
            acc = 0.f; cnt_local = 0; curg = g;
        }
        acc += feats[n * HC + c];
        cnt_local++;
    }
    atomicAdd(&g_pool[curg * HC + c], acc);
    if (c == 0) atomicAdd(&g_cnt[curg], (float)cnt_local);
}

// ---------------- FC + log_softmax ---------------------------------------------
__global__ void final_kernel(const float* __restrict__ fcW, const float* __restrict__ fcb,
                             const float* __restrict__ b2, float* __restrict__ out) {
    __shared__ float sh[128 * 8 + 8];
    int g = blockIdx.x;
    int c = threadIdx.x;
    float cnt = g_cnt[g];
    float mean = 0.f;
    if (cnt > 0.f) mean = g_pool[g * HC + c] / cnt + b2[c];
#pragma unroll
    for (int j = 0; j < 8; ++j) sh[c * 8 + j] = mean * fcW[c * 8 + j];
    __syncthreads();
    if (c < 8) {
        float s = fcb[c];
        for (int k = 0; k < 128; ++k) s += sh[k * 8 + c];
        sh[1024 + c] = s;
    }
    __syncthreads();
    if (c == 0) {
        float mx = sh[1024];
#pragma unroll
        for (int j = 1; j < 8; ++j) mx = fmaxf(mx, sh[1024 + j]);
        float se = 0.f;
#pragma unroll
        for (int j = 0; j < 8; ++j) se += __expf(sh[1024 + j] - mx);
        float lse = logf(se) + mx;
#pragma unroll
        for (int j = 0; j < 8; ++j) out[g * 8 + j] = sh[1024 + j] - lse;
    }
}

// ---------------- launch --------------------------------------------------------
extern "C" void kernel_launch(void* const* d_in, const int* in_sizes, int n_in,
                              void* d_out, int out_size) {
    const float* x        = (const float*)d_in[0];
    const int*   ei       = (const int*)d_in[1];
    const int*   batch    = (const int*)d_in[2];
    const float* W1       = (const float*)d_in[3];
    const float* att_src1 = (const float*)d_in[4];
    const float* att_dst1 = (const float*)d_in[5];
    const float* b1       = (const float*)d_in[6];
    const float* W2       = (const float*)d_in[7];
    const float* att_src2 = (const float*)d_in[8];
    const float* att_dst2 = (const float*)d_in[9];
    const float* b2       = (const float*)d_in[10];
    const float* fcW      = (const float*)d_in[11];
    const float* fcb      = (const float*)d_in[12];
    float*       out      = (float*)d_out;

    const int GB = (N_NODES + 63) / 64;
    const int FB = (E4 + N_NODES + 255) / 256;

    // fork: gemm1 (+zero_pool) overlaps the CSR build
    cudaEventRecord(g_side.e_fork, 0);
    cudaStreamWaitEvent(g_side.s, g_side.e_fork, 0);
    gemm_att_kernel<<<GB, 256, 0, g_side.s>>>(x, W1, att_src1, att_dst1, 1, N_NODES);
    zero_pool_kernel<<<(NGRAPH * HC + 255) / 256, 256, 0, g_side.s>>>();

    zero_deg_kernel<<<(N_NODES + 255) / 256, 256>>>();
    hist_kernel<<<(E4 + 255) / 256, 256>>>(ei);
    scan_kernel<<<1, 1024>>>();
    fill_kernel<<<FB, 256>>>(ei);

    cudaEventRecord(g_side.e_join, g_side.s);
    cudaStreamWaitEvent(0, g_side.e_join, 0);

    agg_kernel<<<(N_NODES + 7) / 8, 256>>>(b1);

    gemm_att_kernel<<<GB, 256>>>(nullptr, W2, att_src2, att_dst2, 0, N_NODES);
    agg_kernel<<<(N_NODES + 7) / 8, 256>>>(nullptr);

    pool_kernel<<<(N_NODES + 127) / 128, 128>>>(batch);
    final_kernel<<<NGRAPH, 128>>>(fcW, fcb, b2, out);
}